// round 1
// baseline (speedup 1.0000x reference)
#include <cuda_runtime.h>
#include <math.h>

#define NB 4
#define NLEN 4096
#define LSEQ 3072
#define CKD 512
#define NLVL 11
#define TWO_PI 6.28318530717958647692f

// ---------------- device scratch (static, no allocation) ----------------
__device__ float g_vA[(size_t)NB * NLEN * CKD];
__device__ float g_vB[(size_t)NB * NLEN * CKD];
__device__ float g_dbuf[(size_t)NB * 2048 * CKD];

#define SPEC_SZ (NLVL * NB * 16 * CKD)
__device__ float g_DfR[SPEC_SZ];
__device__ float g_DfI[SPEC_SZ];
__device__ float g_SfR[SPEC_SZ];
__device__ float g_SfI[SPEC_SZ];
__device__ float g_UdFR[SPEC_SZ];
__device__ float g_UdFI[SPEC_SZ];
__device__ float g_UsFR[SPEC_SZ];
__device__ float g_UsFI[SPEC_SZ];

__device__ float g_Ud[(size_t)NB * NLEN * CKD];
__device__ float g_Us[(size_t)NB * NLEN * CKD];
__device__ float g_Wt[(size_t)6 * 16 * 512 * 512];

// ---------------- GEMM: C[r][n] = sum_k A[map(r)][k]*W[n][k] + bias[n] ----------------
// mode 0: Lk0 with wrap padding (M=16384, src rows from x (B,3072,512))
// mode 1: Lk1 with slice        (M=12288, src rows from v (B,4096,512))
__global__ void __launch_bounds__(256) gemm_kernel(
    const float* __restrict__ A, const float* __restrict__ W,
    const float* __restrict__ bias, float* __restrict__ C,
    int M, int mode)
{
    __shared__ float As[8][128];
    __shared__ float Ws[8][128];
    int tid = threadIdx.x;
    int bm = blockIdx.y * 128, bn = blockIdx.x * 128;
    int lr = tid >> 1;
    int lk = (tid & 1) * 4;

    int gm = bm + lr;
    int srcRow;
    if (mode == 0) {
        int b = gm >> 12; int t = gm & 4095;
        srcRow = b * LSEQ + (t < LSEQ ? t : t - LSEQ);
    } else {
        int b = gm / LSEQ; int t = gm - b * LSEQ;
        srcRow = (b << 12) + t;
    }
    const float* arow = A + (size_t)srcRow * 512 + lk;
    const float* wrow = W + (size_t)(bn + lr) * 512 + lk;

    int tx = tid & 15, ty = tid >> 4;
    float acc[8][8];
#pragma unroll
    for (int i = 0; i < 8; i++)
#pragma unroll
        for (int j = 0; j < 8; j++) acc[i][j] = 0.f;

    for (int k0 = 0; k0 < 512; k0 += 8) {
        float4 av = *(const float4*)(arow + k0);
        float4 wv = *(const float4*)(wrow + k0);
        __syncthreads();
        As[lk + 0][lr] = av.x; As[lk + 1][lr] = av.y; As[lk + 2][lr] = av.z; As[lk + 3][lr] = av.w;
        Ws[lk + 0][lr] = wv.x; Ws[lk + 1][lr] = wv.y; Ws[lk + 2][lr] = wv.z; Ws[lk + 3][lr] = wv.w;
        __syncthreads();
#pragma unroll
        for (int kk = 0; kk < 8; kk++) {
            float4 a0 = *(const float4*)&As[kk][ty * 8];
            float4 a1 = *(const float4*)&As[kk][ty * 8 + 4];
            float4 b0 = *(const float4*)&Ws[kk][tx * 8];
            float4 b1 = *(const float4*)&Ws[kk][tx * 8 + 4];
            float af[8] = {a0.x, a0.y, a0.z, a0.w, a1.x, a1.y, a1.z, a1.w};
            float bf[8] = {b0.x, b0.y, b0.z, b0.w, b1.x, b1.y, b1.z, b1.w};
#pragma unroll
            for (int i = 0; i < 8; i++)
#pragma unroll
                for (int j = 0; j < 8; j++) acc[i][j] += af[i] * bf[j];
        }
    }
#pragma unroll
    for (int i = 0; i < 8; i++) {
        int r = bm + ty * 8 + i;
        float* crow = C + (size_t)r * 512 + bn + tx * 8;
#pragma unroll
        for (int j = 0; j < 8; j++) crow[j] = acc[i][j] + bias[bn + tx * 8 + j];
    }
}

// ---------------- wavelet decomposition filter: d = xa@ec_d, s = xa@ec_s ----------------
__global__ void filter_kernel(const float* __restrict__ vin, float* __restrict__ sout,
                              float* __restrict__ dout, int Lc,
                              const float* __restrict__ ec_s, const float* __restrict__ ec_d)
{
    __shared__ float es[128], ed[128];
    if (threadIdx.x < 128) { es[threadIdx.x] = ec_s[threadIdx.x]; ed[threadIdx.x] = ec_d[threadIdx.x]; }
    __syncthreads();
    int idx = blockIdx.x * 256 + threadIdx.x;
    if (idx >= NB * Lc * 64) return;
    int c = idx & 63;
    int bt = idx >> 6;
    int t = bt % Lc;
    int b = bt / Lc;

    const float4* p0 = (const float4*)(vin + ((size_t)b * NLEN + 2 * t) * 512 + c * 8);
    const float4* p1 = (const float4*)(vin + ((size_t)b * NLEN + 2 * t + 1) * 512 + c * 8);
    float4 x0 = p0[0], x1 = p0[1], x2 = p1[0], x3 = p1[1];
    float xa[16] = {x0.x, x0.y, x0.z, x0.w, x1.x, x1.y, x1.z, x1.w,
                    x2.x, x2.y, x2.z, x2.w, x3.x, x3.y, x3.z, x3.w};
    float dv[8] = {0}, sv[8] = {0};
#pragma unroll
    for (int kk = 0; kk < 16; kk++) {
        float xv = xa[kk];
#pragma unroll
        for (int k = 0; k < 8; k++) {
            dv[k] += xv * ed[kk * 8 + k];
            sv[k] += xv * es[kk * 8 + k];
        }
    }
    float* dd = dout + ((size_t)b * Lc + t) * 512 + c * 8;
    float* ss = sout + ((size_t)b * NLEN + t) * 512 + c * 8;
    ((float4*)dd)[0] = make_float4(dv[0], dv[1], dv[2], dv[3]);
    ((float4*)dd)[1] = make_float4(dv[4], dv[5], dv[6], dv[7]);
    ((float4*)ss)[0] = make_float4(sv[0], sv[1], sv[2], sv[3]);
    ((float4*)ss)[1] = make_float4(sv[4], sv[5], sv[6], sv[7]);
}

// ---------------- forward partial DFT (16 modes) for d and s ----------------
// grid: x = b*8 + channel-chunk, y = tensor (0=d from dbuf, 1=s from sbuf); block = 1024 = 64 ch x 16 modes
__global__ void __launch_bounds__(1024) fwd_dft_kernel(
    int lvl, int Lc, const float* __restrict__ dbuf, const float* __restrict__ sbuf,
    float* __restrict__ DfR, float* __restrict__ DfI,
    float* __restrict__ SfR, float* __restrict__ SfI)
{
    int b = blockIdx.x >> 3, ic = blockIdx.x & 7;
    int iL = threadIdx.x & 63, m = threadIdx.x >> 6;
    const float* base;
    if (blockIdx.y == 0) base = dbuf + (size_t)b * Lc * 512 + ic * 64;
    else                 base = sbuf + (size_t)b * NLEN * 512 + ic * 64;

    __shared__ float xs[32][64];
    __shared__ float cc[32][16], ssm[32][16];
    float accR = 0.f, accI = 0.f;
    float w = TWO_PI / (float)Lc;

    for (int t0 = 0; t0 < Lc; t0 += 32) {
        __syncthreads();
        for (int idx = threadIdx.x; idx < 2048; idx += 1024) {
            int tt = idx >> 6, ii = idx & 63;
            int t = t0 + tt;
            xs[tt][ii] = (t < Lc) ? base[(size_t)t * 512 + ii] : 0.f;
        }
        if (threadIdx.x < 512) {
            int tt = threadIdx.x >> 4, mm = threadIdx.x & 15;
            float ang = w * (float)(mm * (t0 + tt));
            float sv, cv;
            sincosf(ang, &sv, &cv);
            cc[tt][mm] = cv; ssm[tt][mm] = sv;
        }
        __syncthreads();
#pragma unroll 8
        for (int tt = 0; tt < 32; tt++) {
            float xv = xs[tt][iL];
            accR += xv * cc[tt][m];
            accI -= xv * ssm[tt][m];
        }
    }
    size_t oidx = (((size_t)lvl * 4 + b) * 16 + m) * 512 + ic * 64 + iL;
    if (blockIdx.y == 0) { DfR[oidx] = accR; DfI[oidx] = accI; }
    else                 { SfR[oidx] = accR; SfI[oidx] = accI; }
}

// ---------------- weight transpose: W[i][o][m] -> Wt[arr][m][i*512+o] ----------------
__global__ void transpose_w(const float* __restrict__ Ar, const float* __restrict__ Ai,
                            const float* __restrict__ Br, const float* __restrict__ Bi,
                            const float* __restrict__ Cr, const float* __restrict__ Ci,
                            float* __restrict__ Wt)
{
    const float* src;
    switch (blockIdx.y) {
        case 0: src = Ar; break; case 1: src = Ai; break; case 2: src = Br; break;
        case 3: src = Bi; break; case 4: src = Cr; break; default: src = Ci; break;
    }
    float* dst = Wt + (size_t)blockIdx.y * 16 * 262144;
    int io0 = blockIdx.x * 64;
    __shared__ float sm[64][17];
    int t = threadIdx.x;
    {
        int ioL = t >> 2; int mq = (t & 3) * 4;
        float4 v = *(const float4*)(src + (size_t)(io0 + ioL) * 16 + mq);
        sm[ioL][mq] = v.x; sm[ioL][mq + 1] = v.y; sm[ioL][mq + 2] = v.z; sm[ioL][mq + 3] = v.w;
    }
    __syncthreads();
    {
        int m = t >> 4; int g = (t & 15) * 4;
        float* d2 = dst + (size_t)m * 262144 + io0 + g;
        d2[0] = sm[g][m]; d2[1] = sm[g + 1][m]; d2[2] = sm[g + 2][m]; d2[3] = sm[g + 3][m];
    }
}

// ---------------- spectral mode mixing, batched over all 44 (level,batch) rows ----------------
// grid: (m=16, o_tile=8); block 256 = 64 o x 4 row-groups; each thread handles 11 rows
__global__ void __launch_bounds__(256) mix_kernel(
    const float* __restrict__ Wt,
    const float* __restrict__ DfR, const float* __restrict__ DfI,
    const float* __restrict__ SfR, const float* __restrict__ SfI,
    float* __restrict__ UdFR, float* __restrict__ UdFI,
    float* __restrict__ UsFR, float* __restrict__ UsFI)
{
    int m = blockIdx.x;
    int o0 = blockIdx.y * 64;
    int tx = threadIdx.x & 63;
    int ty = threadIdx.x >> 6;

    __shared__ float wS[6][16][64];   // [arr][ii][o]
    __shared__ float xS[4][44][16];   // [comp][row][ii]

    float aUdR[11], aUdI[11], aUsR[11], aUsI[11];
#pragma unroll
    for (int r = 0; r < 11; r++) { aUdR[r] = 0; aUdI[r] = 0; aUsR[r] = 0; aUsI[r] = 0; }

    for (int i0 = 0; i0 < 512; i0 += 16) {
        __syncthreads();
        for (int idx = threadIdx.x; idx < 6 * 16 * 64; idx += 256) {
            int arr = idx >> 10; int rem = idx & 1023; int ii = rem >> 6; int oo = rem & 63;
            wS[arr][ii][oo] = Wt[((size_t)arr * 16 + m) * 262144 + (size_t)(i0 + ii) * 512 + o0 + oo];
        }
        for (int idx = threadIdx.x; idx < 44 * 16 * 4; idx += 256) {
            int comp = idx / 704; int rem = idx - comp * 704; int r = rem >> 4; int ii = rem & 15;
            const float* src = (comp == 0) ? DfR : (comp == 1) ? DfI : (comp == 2) ? SfR : SfI;
            xS[comp][r][ii] = src[((size_t)r * 16 + m) * 512 + i0 + ii];
        }
        __syncthreads();
#pragma unroll
        for (int ii = 0; ii < 16; ii++) {
            float ar = wS[0][ii][tx], ai = wS[1][ii][tx];
            float br = wS[2][ii][tx], bi = wS[3][ii][tx];
            float cr = wS[4][ii][tx], ci = wS[5][ii][tx];
#pragma unroll
            for (int rr = 0; rr < 11; rr++) {
                int r = ty + rr * 4;
                float dr = xS[0][r][ii], di = xS[1][r][ii];
                float sr = xS[2][r][ii], si = xS[3][r][ii];
                aUdR[rr] += dr * ar - di * ai + sr * br - si * bi;
                aUdI[rr] += dr * ai + di * ar + sr * bi + si * br;
                aUsR[rr] += dr * cr - di * ci;
                aUsI[rr] += dr * ci + di * cr;
            }
        }
    }
#pragma unroll
    for (int rr = 0; rr < 11; rr++) {
        int r = ty + rr * 4;
        size_t idx = ((size_t)r * 16 + m) * 512 + o0 + tx;
        UdFR[idx] = aUdR[rr]; UdFI[idx] = aUdI[rr];
        UsFR[idx] = aUsR[rr]; UsFI[idx] = aUsI[rr];
    }
}

// ---------------- inverse partial DFT (cuFFT c2r semantics: Im of DC & Nyquist dropped) ----------------
__global__ void inv_dft_kernel(int lvl, int Lc, int l, int nyq, int base_t,
                               const float* __restrict__ UdFR, const float* __restrict__ UdFI,
                               const float* __restrict__ UsFR, const float* __restrict__ UsFI,
                               float* __restrict__ Ud, float* __restrict__ Us)
{
    int b = blockIdx.x / Lc;
    int t = blockIdx.x - b * Lc;
    __shared__ float csc[16], css[16];
    if (threadIdx.x < 16) {
        int m = threadIdx.x;
        bool isNyq = nyq && (m == l - 1);
        float fac = (m == 0 || isNyq) ? 1.f : 2.f;
        if (m >= l) fac = 0.f;
        float ang = (TWO_PI / (float)Lc) * (float)(m * t);
        float sv, cv;
        sincosf(ang, &sv, &cv);
        float inv = 1.f / (float)Lc;
        csc[m] = fac * cv * inv;
        css[m] = (m == 0 || isNyq) ? 0.f : -fac * sv * inv;
    }
    __syncthreads();
    int o = threadIdx.x;
    size_t sbase = (((size_t)lvl * 4 + b) * 16) * 512 + o;
    float aUd = 0.f, aUs = 0.f;
    for (int m = 0; m < l; m++) {
        float c = csc[m], s = css[m];
        size_t idx = sbase + (size_t)m * 512;
        aUd += c * UdFR[idx] + s * UdFI[idx];
        aUs += c * UsFR[idx] + s * UsFI[idx];
    }
    size_t oo = ((size_t)b * NLEN + base_t + t) * 512 + o;
    Ud[oo] = aUd;
    Us[oo] = aUs;
}

// ---------------- T0 (K->K linear on coarsest scale, in-place) ----------------
__global__ void t0_kernel(float* __restrict__ v, const float* __restrict__ T0_w,
                          const float* __restrict__ T0_b)
{
    int idx = threadIdx.x;  // 512 = 4b * 2t * 64c
    int c = idx & 63; int bt = idx >> 6; int t = bt & 1; int b = bt >> 1;
    float* p = v + ((size_t)b * NLEN + t) * 512 + c * 8;
    float in[8];
#pragma unroll
    for (int k = 0; k < 8; k++) in[k] = p[k];
#pragma unroll
    for (int k = 0; k < 8; k++) {
        float s = T0_b[k];
#pragma unroll
        for (int kp = 0; kp < 8; kp++) s += T0_w[k * 8 + kp] * in[kp];
        p[k] = s;
    }
}

// ---------------- reconstruction: ve=[v+Us, Ud]; xe=ve@rc_e, xo=ve@rc_o; interleave ----------------
__global__ void recon_kernel(const float* __restrict__ vin, float* __restrict__ vout,
                             const float* __restrict__ Ud, const float* __restrict__ Us,
                             int Lc, int base_t,
                             const float* __restrict__ rc_e, const float* __restrict__ rc_o)
{
    __shared__ float re[128], ro[128];
    if (threadIdx.x < 128) { re[threadIdx.x] = rc_e[threadIdx.x]; ro[threadIdx.x] = rc_o[threadIdx.x]; }
    __syncthreads();
    int idx = blockIdx.x * 256 + threadIdx.x;
    if (idx >= NB * Lc * 64) return;
    int c = idx & 63;
    int bt = idx >> 6;
    int t = bt % Lc;
    int b = bt / Lc;

    size_t vofs = ((size_t)b * NLEN + t) * 512 + c * 8;
    size_t uofs = ((size_t)b * NLEN + base_t + t) * 512 + c * 8;
    float ve[16];
#pragma unroll
    for (int k = 0; k < 8; k++) {
        ve[k] = vin[vofs + k] + Us[uofs + k];
        ve[8 + k] = Ud[uofs + k];
    }
    float xe[8] = {0}, xo[8] = {0};
#pragma unroll
    for (int kk = 0; kk < 16; kk++) {
        float xv = ve[kk];
#pragma unroll
        for (int k = 0; k < 8; k++) {
            xe[k] += xv * re[kk * 8 + k];
            xo[k] += xv * ro[kk * 8 + k];
        }
    }
    float* d0 = vout + ((size_t)b * NLEN + 2 * t) * 512 + c * 8;
    float* d1 = d0 + 512;
    ((float4*)d0)[0] = make_float4(xe[0], xe[1], xe[2], xe[3]);
    ((float4*)d0)[1] = make_float4(xe[4], xe[5], xe[6], xe[7]);
    ((float4*)d1)[0] = make_float4(xo[0], xo[1], xo[2], xo[3]);
    ((float4*)d1)[1] = make_float4(xo[4], xo[5], xo[6], xo[7]);
}

// ---------------- host orchestration ----------------
extern "C" void kernel_launch(void* const* d_in, const int* in_sizes, int n_in,
                              void* d_out, int out_size)
{
    const float* x     = (const float*)d_in[0];
    const float* Lk0_w = (const float*)d_in[1];
    const float* Lk0_b = (const float*)d_in[2];
    const float* Lk1_w = (const float*)d_in[3];
    const float* Lk1_b = (const float*)d_in[4];
    const float* T0_w  = (const float*)d_in[5];
    const float* T0_b  = (const float*)d_in[6];
    const float* Ar    = (const float*)d_in[7];
    const float* Ai    = (const float*)d_in[8];
    const float* Br    = (const float*)d_in[9];
    const float* Bi    = (const float*)d_in[10];
    const float* Cr    = (const float*)d_in[11];
    const float* Ci    = (const float*)d_in[12];
    const float* ec_s  = (const float*)d_in[13];
    const float* ec_d  = (const float*)d_in[14];
    const float* rc_e  = (const float*)d_in[15];
    const float* rc_o  = (const float*)d_in[16];

    float *vA, *vB, *dbuf, *DfR, *DfI, *SfR, *SfI, *UdFR, *UdFI, *UsFR, *UsFI, *Ud, *Us, *Wt;
    cudaGetSymbolAddress((void**)&vA, g_vA);
    cudaGetSymbolAddress((void**)&vB, g_vB);
    cudaGetSymbolAddress((void**)&dbuf, g_dbuf);
    cudaGetSymbolAddress((void**)&DfR, g_DfR);
    cudaGetSymbolAddress((void**)&DfI, g_DfI);
    cudaGetSymbolAddress((void**)&SfR, g_SfR);
    cudaGetSymbolAddress((void**)&SfI, g_SfI);
    cudaGetSymbolAddress((void**)&UdFR, g_UdFR);
    cudaGetSymbolAddress((void**)&UdFI, g_UdFI);
    cudaGetSymbolAddress((void**)&UsFR, g_UsFR);
    cudaGetSymbolAddress((void**)&UsFI, g_UsFI);
    cudaGetSymbolAddress((void**)&Ud, g_Ud);
    cudaGetSymbolAddress((void**)&Us, g_Us);
    cudaGetSymbolAddress((void**)&Wt, g_Wt);

    // 1. transpose spectral weights (independent of everything else)
    transpose_w<<<dim3(4096, 6), 256>>>(Ar, Ai, Br, Bi, Cr, Ci, Wt);

    // 2. Lk0 GEMM with wrap padding -> vA (B,4096,512)
    gemm_kernel<<<dim3(4, 128), 256>>>(x, Lk0_w, Lk0_b, vA, NB * NLEN, 0);

    // 3. decomposition: 11 levels of (filter -> partial forward DFT of d and s)
    float* cur = vA;
    float* oth = vB;
    for (int j = 0; j < NLVL; j++) {
        int Lc = NLEN >> (j + 1);
        int nblk = (NB * Lc * 64 + 255) / 256;
        filter_kernel<<<nblk, 256>>>(cur, oth, dbuf, Lc, ec_s, ec_d);
        fwd_dft_kernel<<<dim3(32, 2), 1024>>>(j, Lc, dbuf, oth, DfR, DfI, SfR, SfI);
        float* tmp = cur; cur = oth; oth = tmp;
    }

    // 4. one batched spectral mixing over all 44 (level,batch) rows — weights read once
    mix_kernel<<<dim3(16, 8), 256>>>(Wt, DfR, DfI, SfR, SfI, UdFR, UdFI, UsFR, UsFI);

    // 5. inverse partial DFTs per level -> Ud, Us time-domain buffers
    for (int j = 0; j < NLVL; j++) {
        int Lc = NLEN >> (j + 1);
        int nf = (Lc >> 1) + 1;
        int l = nf < 16 ? nf : 16;
        int nyq = (l == nf) ? 1 : 0;
        int base = NLEN - (NLEN >> j);
        inv_dft_kernel<<<NB * Lc, 512>>>(j, Lc, l, nyq, base,
                                         UdFR, UdFI, UsFR, UsFI, Ud, Us);
    }

    // 6. T0 on coarsest scale (in-place in cur)
    t0_kernel<<<1, 512>>>(cur, T0_w, T0_b);

    // 7. reconstruction: 11 levels coarse -> fine
    for (int i = NLVL - 1; i >= 0; i--) {
        int Lc = NLEN >> (i + 1);
        int base = NLEN - (NLEN >> i);
        int nblk = (NB * Lc * 64 + 255) / 256;
        recon_kernel<<<nblk, 256>>>(cur, oth, Ud, Us, Lc, base, rc_e, rc_o);
        float* tmp = cur; cur = oth; oth = tmp;
    }

    // 8. Lk1 GEMM (slice t<3072 fused) -> d_out
    gemm_kernel<<<dim3(4, 96), 256>>>(cur, Lk1_w, Lk1_b, (float*)d_out, NB * LSEQ, 1);
}

// round 2
// speedup vs baseline: 1.2228x; 1.2228x over previous
#include <cuda_runtime.h>
#include <math.h>

#define NB 4
#define NLEN 4096
#define LSEQ 3072
#define CKD 512
#define NLVL 11
#define TWO_PI 6.28318530717958647692f

typedef unsigned long long u64;

// ---------------- f32x2 helpers (Blackwell packed fp32) ----------------
__device__ __forceinline__ u64 pk(float x, float y) {
    u64 r; asm("mov.b64 %0, {%1, %2};" : "=l"(r) : "f"(x), "f"(y)); return r;
}
__device__ __forceinline__ void upk(u64 v, float& x, float& y) {
    asm("mov.b64 {%0, %1}, %2;" : "=f"(x), "=f"(y) : "l"(v));
}
__device__ __forceinline__ u64 f2(u64 a, u64 b, u64 c) {
    u64 d; asm("fma.rn.f32x2 %0, %1, %2, %3;" : "=l"(d) : "l"(a), "l"(b), "l"(c)); return d;
}

// ---------------- device scratch ----------------
__device__ float g_vA[(size_t)NB * NLEN * CKD];
__device__ float g_vB[(size_t)NB * NLEN * CKD];
__device__ float g_dbuf[(size_t)NB * 2048 * CKD];

#define SPEC_SZ (NLVL * NB * 16 * CKD)
__device__ float g_DfR[SPEC_SZ];
__device__ float g_DfI[SPEC_SZ];
__device__ float g_SfR[SPEC_SZ];
__device__ float g_SfI[SPEC_SZ];
__device__ float g_UdFR[SPEC_SZ];
__device__ float g_UdFI[SPEC_SZ];
__device__ float g_UsFR[SPEC_SZ];
__device__ float g_UsFI[SPEC_SZ];

__device__ float g_Ud[(size_t)NB * NLEN * CKD];
__device__ float g_Us[(size_t)NB * NLEN * CKD];
__device__ float g_Wt[(size_t)6 * 16 * 512 * 512];
__device__ float2 g_tw[16 * 4096];
__device__ u64 g_part[8 * 8 * 16 * 512];

// ---------------- twiddle tables for all levels ----------------
__global__ void twiddle_kernel(float2* __restrict__ tw) {
    int j = blockIdx.y;
    int Lc = NLEN >> (j + 1);
    int idx = blockIdx.x * 256 + threadIdx.x;
    if (idx >= Lc * 16) return;
    int t = idx >> 4, m = idx & 15;
    int toff = 16 * (4096 - (4096 >> j));
    float ang = (TWO_PI / (float)Lc) * (float)(m * t);
    float sv, cv;
    sincosf(ang, &sv, &cv);
    tw[toff + idx] = make_float2(cv, sv);
}

// ---------------- GEMM with f32x2 packed inner product ----------------
__global__ void __launch_bounds__(256) gemm_kernel(
    const float* __restrict__ A, const float* __restrict__ W,
    const float* __restrict__ bias, float* __restrict__ C,
    int M, int mode)
{
    __shared__ float As[8][128];
    __shared__ float Ws[8][128];
    int tid = threadIdx.x;
    int bm = blockIdx.y * 128, bn = blockIdx.x * 128;
    int lr = tid >> 1;
    int lk = (tid & 1) * 4;

    int gm = bm + lr;
    int srcRow;
    if (mode == 0) {
        int b = gm >> 12; int t = gm & 4095;
        srcRow = b * LSEQ + (t < LSEQ ? t : t - LSEQ);
    } else {
        int b = gm / LSEQ; int t = gm - b * LSEQ;
        srcRow = (b << 12) + t;
    }
    const float* arow = A + (size_t)srcRow * 512 + lk;
    const float* wrow = W + (size_t)(bn + lr) * 512 + lk;

    int tx = tid & 15, ty = tid >> 4;
    u64 acc[8][4];
#pragma unroll
    for (int i = 0; i < 8; i++)
#pragma unroll
        for (int j = 0; j < 4; j++) acc[i][j] = 0ull;

    for (int k0 = 0; k0 < 512; k0 += 8) {
        float4 av = *(const float4*)(arow + k0);
        float4 wv = *(const float4*)(wrow + k0);
        __syncthreads();
        As[lk + 0][lr] = av.x; As[lk + 1][lr] = av.y; As[lk + 2][lr] = av.z; As[lk + 3][lr] = av.w;
        Ws[lk + 0][lr] = wv.x; Ws[lk + 1][lr] = wv.y; Ws[lk + 2][lr] = wv.z; Ws[lk + 3][lr] = wv.w;
        __syncthreads();
#pragma unroll
        for (int kk = 0; kk < 8; kk++) {
            const u64* wsp = (const u64*)&Ws[kk][tx * 8];
            u64 b0 = wsp[0], b1 = wsp[1], b2 = wsp[2], b3 = wsp[3];
            const float* asp = &As[kk][ty * 8];
#pragma unroll
            for (int i = 0; i < 8; i++) {
                float a = asp[i];
                u64 aa = pk(a, a);
                acc[i][0] = f2(aa, b0, acc[i][0]);
                acc[i][1] = f2(aa, b1, acc[i][1]);
                acc[i][2] = f2(aa, b2, acc[i][2]);
                acc[i][3] = f2(aa, b3, acc[i][3]);
            }
        }
    }
#pragma unroll
    for (int i = 0; i < 8; i++) {
        int r = bm + ty * 8 + i;
        float* crow = C + (size_t)r * 512 + bn + tx * 8;
#pragma unroll
        for (int jp = 0; jp < 4; jp++) {
            float v0, v1;
            upk(acc[i][jp], v0, v1);
            crow[2 * jp]     = v0 + bias[bn + tx * 8 + 2 * jp];
            crow[2 * jp + 1] = v1 + bias[bn + tx * 8 + 2 * jp + 1];
        }
    }
}

// ---------------- wavelet decomposition filter ----------------
__global__ void filter_kernel(const float* __restrict__ vin, float* __restrict__ sout,
                              float* __restrict__ dout, int Lc,
                              const float* __restrict__ ec_s, const float* __restrict__ ec_d)
{
    __shared__ float es[128], ed[128];
    if (threadIdx.x < 128) { es[threadIdx.x] = ec_s[threadIdx.x]; ed[threadIdx.x] = ec_d[threadIdx.x]; }
    __syncthreads();
    int idx = blockIdx.x * 256 + threadIdx.x;
    if (idx >= NB * Lc * 64) return;
    int c = idx & 63;
    int bt = idx >> 6;
    int t = bt % Lc;
    int b = bt / Lc;

    const float4* p0 = (const float4*)(vin + ((size_t)b * NLEN + 2 * t) * 512 + c * 8);
    const float4* p1 = (const float4*)(vin + ((size_t)b * NLEN + 2 * t + 1) * 512 + c * 8);
    float4 x0 = p0[0], x1 = p0[1], x2 = p1[0], x3 = p1[1];
    float xa[16] = {x0.x, x0.y, x0.z, x0.w, x1.x, x1.y, x1.z, x1.w,
                    x2.x, x2.y, x2.z, x2.w, x3.x, x3.y, x3.z, x3.w};
    float dv[8] = {0}, sv[8] = {0};
#pragma unroll
    for (int kk = 0; kk < 16; kk++) {
        float xv = xa[kk];
#pragma unroll
        for (int k = 0; k < 8; k++) {
            dv[k] += xv * ed[kk * 8 + k];
            sv[k] += xv * es[kk * 8 + k];
        }
    }
    float* dd = dout + ((size_t)b * Lc + t) * 512 + c * 8;
    float* ss = sout + ((size_t)b * NLEN + t) * 512 + c * 8;
    ((float4*)dd)[0] = make_float4(dv[0], dv[1], dv[2], dv[3]);
    ((float4*)dd)[1] = make_float4(dv[4], dv[5], dv[6], dv[7]);
    ((float4*)ss)[0] = make_float4(sv[0], sv[1], sv[2], sv[3]);
    ((float4*)ss)[1] = make_float4(sv[4], sv[5], sv[6], sv[7]);
}

// ---------------- forward partial DFT v2: split-T, packed, partials ----------------
// grid: x = b*8+ic (32), y = tensor (2), z = chunk (gz); block 256 = 64ch x 4 mode-groups
__global__ void __launch_bounds__(256) fwd_dft2(
    int Lc, int CH, int toff,
    const float* __restrict__ dbuf, const float* __restrict__ sbuf,
    const float2* __restrict__ tw, u64* __restrict__ part)
{
    int b = blockIdx.x >> 3, ic = blockIdx.x & 7;
    int tensor = blockIdx.y;
    int cz = blockIdx.z;
    const float* base = (tensor == 0) ? dbuf + (size_t)b * Lc * 512 + ic * 64
                                      : sbuf + (size_t)b * NLEN * 512 + ic * 64;
    int iL = threadIdx.x & 63, mg = threadIdx.x >> 6;

    __shared__ float xs[32][64];
    __shared__ u64 tws[32][16];
    u64 acc[4] = {0ull, 0ull, 0ull, 0ull};

    int t0base = cz * CH;
    for (int t0 = t0base; t0 < t0base + CH; t0 += 32) {
        __syncthreads();
#pragma unroll
        for (int r = 0; r < 8; r++) {
            int idx = threadIdx.x + r * 256;
            int tt = idx >> 6, ii = idx & 63;
            int t = t0 + tt;
            xs[tt][ii] = (t < Lc) ? base[(size_t)t * 512 + ii] : 0.f;
        }
#pragma unroll
        for (int r = 0; r < 2; r++) {
            int idx = threadIdx.x + r * 256;
            int tt = idx >> 4, mm = idx & 15;
            int t = t0 + tt;
            float2 cs = (t < Lc) ? tw[toff + t * 16 + mm] : make_float2(0.f, 0.f);
            tws[tt][mm] = pk(cs.x, -cs.y);
        }
        __syncthreads();
#pragma unroll 8
        for (int tt = 0; tt < 32; tt++) {
            float xv = xs[tt][iL];
            u64 xx = pk(xv, xv);
            const u64* twr = &tws[tt][mg * 4];
            acc[0] = f2(xx, twr[0], acc[0]);
            acc[1] = f2(xx, twr[1], acc[1]);
            acc[2] = f2(xx, twr[2], acc[2]);
            acc[3] = f2(xx, twr[3], acc[3]);
        }
    }
    int tb = tensor * 4 + b;
    size_t pbase = ((size_t)(tb * 8 + cz) << 13);
#pragma unroll
    for (int k = 0; k < 4; k++) {
        int m = mg * 4 + k;
        part[pbase + m * 512 + ic * 64 + iL] = acc[k];
    }
}

// reduce partials -> Df / Sf
__global__ void reduce_fwd(const u64* __restrict__ part, int gz, int lvl,
                           float* __restrict__ DfR, float* __restrict__ DfI,
                           float* __restrict__ SfR, float* __restrict__ SfI)
{
    int idx = blockIdx.x * 256 + threadIdx.x;
    if (idx >= 65536) return;
    int tb = idx >> 13;
    int rem = idx & 8191;
    float sR = 0.f, sI = 0.f;
    for (int cz = 0; cz < gz; cz++) {
        float x, y;
        upk(part[((size_t)(tb * 8 + cz) << 13) + rem], x, y);
        sR += x; sI += y;
    }
    int tensor = tb >> 2, b = tb & 3;
    size_t o = (((size_t)lvl * 4 + b) * 16) * 512 + rem;
    if (tensor == 0) { DfR[o] = sR; DfI[o] = sI; }
    else             { SfR[o] = sR; SfI[o] = sI; }
}

// ---------------- weight transpose ----------------
__global__ void transpose_w(const float* __restrict__ Ar, const float* __restrict__ Ai,
                            const float* __restrict__ Br, const float* __restrict__ Bi,
                            const float* __restrict__ Cr, const float* __restrict__ Ci,
                            float* __restrict__ Wt)
{
    const float* src;
    switch (blockIdx.y) {
        case 0: src = Ar; break; case 1: src = Ai; break; case 2: src = Br; break;
        case 3: src = Bi; break; case 4: src = Cr; break; default: src = Ci; break;
    }
    float* dst = Wt + (size_t)blockIdx.y * 16 * 262144;
    int io0 = blockIdx.x * 64;
    __shared__ float sm[64][17];
    int t = threadIdx.x;
    {
        int ioL = t >> 2; int mq = (t & 3) * 4;
        float4 v = *(const float4*)(src + (size_t)(io0 + ioL) * 16 + mq);
        sm[ioL][mq] = v.x; sm[ioL][mq + 1] = v.y; sm[ioL][mq + 2] = v.z; sm[ioL][mq + 3] = v.w;
    }
    __syncthreads();
    {
        int m = t >> 4; int g = (t & 15) * 4;
        float* d2 = dst + (size_t)m * 262144 + io0 + g;
        d2[0] = sm[g][m]; d2[1] = sm[g + 1][m]; d2[2] = sm[g + 2][m]; d2[3] = sm[g + 3][m];
    }
}

// ---------------- spectral mode mixing with f32x2 ----------------
__global__ void __launch_bounds__(256) mix_kernel(
    const float* __restrict__ Wt,
    const float* __restrict__ DfR, const float* __restrict__ DfI,
    const float* __restrict__ SfR, const float* __restrict__ SfI,
    float* __restrict__ UdFR, float* __restrict__ UdFI,
    float* __restrict__ UsFR, float* __restrict__ UsFI)
{
    int m = blockIdx.x;
    int o0 = blockIdx.y * 64;
    int tx = threadIdx.x & 63;
    int ty = threadIdx.x >> 6;

    __shared__ float wS[6][16][64];
    __shared__ u64 xP[4][44][16];

    u64 aUd[11], aUs[11];
#pragma unroll
    for (int r = 0; r < 11; r++) { aUd[r] = 0ull; aUs[r] = 0ull; }

    for (int i0 = 0; i0 < 512; i0 += 16) {
        __syncthreads();
        for (int idx = threadIdx.x; idx < 6 * 16 * 64; idx += 256) {
            int arr = idx >> 10; int rem = idx & 1023; int ii = rem >> 6; int oo = rem & 63;
            wS[arr][ii][oo] = Wt[((size_t)arr * 16 + m) * 262144 + (size_t)(i0 + ii) * 512 + o0 + oo];
        }
        for (int idx = threadIdx.x; idx < 44 * 16 * 4; idx += 256) {
            int comp = idx / 704; int rem = idx - comp * 704; int r = rem >> 4; int ii = rem & 15;
            const float* src = (comp == 0) ? DfR : (comp == 1) ? DfI : (comp == 2) ? SfR : SfI;
            float v = src[((size_t)r * 16 + m) * 512 + i0 + ii];
            xP[comp][r][ii] = pk(v, v);
        }
        __syncthreads();
#pragma unroll
        for (int ii = 0; ii < 16; ii++) {
            float ar = wS[0][ii][tx], ai = wS[1][ii][tx];
            float br = wS[2][ii][tx], bi = wS[3][ii][tx];
            float cr = wS[4][ii][tx], ci = wS[5][ii][tx];
            u64 wa  = pk(ar, ai),  wan = pk(-ai, ar);
            u64 wb  = pk(br, bi),  wbn = pk(-bi, br);
            u64 wc  = pk(cr, ci),  wcn = pk(-ci, cr);
#pragma unroll
            for (int rr = 0; rr < 11; rr++) {
                int r = ty + rr * 4;
                u64 dd = xP[0][r][ii], di2 = xP[1][r][ii];
                u64 ss2 = xP[2][r][ii], si2 = xP[3][r][ii];
                aUd[rr] = f2(dd, wa, f2(di2, wan, f2(ss2, wb, f2(si2, wbn, aUd[rr]))));
                aUs[rr] = f2(dd, wc, f2(di2, wcn, aUs[rr]));
            }
        }
    }
#pragma unroll
    for (int rr = 0; rr < 11; rr++) {
        int r = ty + rr * 4;
        size_t idx = ((size_t)r * 16 + m) * 512 + o0 + tx;
        float x, y;
        upk(aUd[rr], x, y); UdFR[idx] = x; UdFI[idx] = y;
        upk(aUs[rr], x, y); UsFR[idx] = x; UsFI[idx] = y;
    }
}

// ---------------- inverse partial DFT v2: spectral in regs, split-T ----------------
// grid: (ot=8, b=4, cz=gz); block 256 = 64 o x 4 t-groups
__global__ void __launch_bounds__(256) inv_dft2(
    int lvl, int Lc, int l, int nyq, int base_t, int CH, int toff,
    const float* __restrict__ UdFR, const float* __restrict__ UdFI,
    const float* __restrict__ UsFR, const float* __restrict__ UsFI,
    const float2* __restrict__ tw,
    float* __restrict__ Ud, float* __restrict__ Us)
{
    int ot = blockIdx.x;
    int b = blockIdx.y;
    int cz = blockIdx.z;
    int oL = threadIdx.x & 63, tg = threadIdx.x >> 6;
    int o = ot * 64 + oL;
    size_t sb = (((size_t)lvl * 4 + b) * 16) * 512 + o;

    u64 vUd[16], vUs[16];
#pragma unroll
    for (int mm = 0; mm < 16; mm++) {
        size_t ix = sb + (size_t)mm * 512;
        vUd[mm] = pk(UdFR[ix], UdFI[ix]);
        vUs[mm] = pk(UsFR[ix], UsFI[ix]);
    }

    __shared__ u64 cs[32][16];
    float invL = 1.f / (float)Lc;
    int t0base = cz * CH;
    for (int t0 = t0base; t0 < t0base + CH; t0 += 32) {
        __syncthreads();
#pragma unroll
        for (int r = 0; r < 2; r++) {
            int idx = threadIdx.x + r * 256;
            int tt = idx >> 4, mm = idx & 15;
            int t = t0 + tt;
            float cp = 0.f, sp = 0.f;
            if (t < Lc && mm < l) {
                float2 w = tw[toff + t * 16 + mm];
                bool spec = (mm == 0) || (nyq && mm == l - 1);
                float fac = spec ? 1.f : 2.f;
                cp = fac * w.x * invL;
                sp = spec ? 0.f : -fac * w.y * invL;
            }
            cs[tt][mm] = pk(cp, sp);
        }
        __syncthreads();
        for (int tt = tg; tt < 32; tt += 4) {
            int t = t0 + tt;
            if (t < Lc) {
                u64 aU = 0ull, aS = 0ull;
#pragma unroll
                for (int mm = 0; mm < 16; mm++) {
                    u64 c = cs[tt][mm];
                    aU = f2(c, vUd[mm], aU);
                    aS = f2(c, vUs[mm], aS);
                }
                float ux, uy, sx, sy;
                upk(aU, ux, uy); upk(aS, sx, sy);
                size_t oo = ((size_t)b * NLEN + base_t + t) * 512 + o;
                Ud[oo] = ux + uy;
                Us[oo] = sx + sy;
            }
        }
    }
}

// ---------------- T0 ----------------
__global__ void t0_kernel(float* __restrict__ v, const float* __restrict__ T0_w,
                          const float* __restrict__ T0_b)
{
    int idx = threadIdx.x;
    int c = idx & 63; int bt = idx >> 6; int t = bt & 1; int b = bt >> 1;
    float* p = v + ((size_t)b * NLEN + t) * 512 + c * 8;
    float in[8];
#pragma unroll
    for (int k = 0; k < 8; k++) in[k] = p[k];
#pragma unroll
    for (int k = 0; k < 8; k++) {
        float s = T0_b[k];
#pragma unroll
        for (int kp = 0; kp < 8; kp++) s += T0_w[k * 8 + kp] * in[kp];
        p[k] = s;
    }
}

// ---------------- reconstruction ----------------
__global__ void recon_kernel(const float* __restrict__ vin, float* __restrict__ vout,
                             const float* __restrict__ Ud, const float* __restrict__ Us,
                             int Lc, int base_t,
                             const float* __restrict__ rc_e, const float* __restrict__ rc_o)
{
    __shared__ float re[128], ro[128];
    if (threadIdx.x < 128) { re[threadIdx.x] = rc_e[threadIdx.x]; ro[threadIdx.x] = rc_o[threadIdx.x]; }
    __syncthreads();
    int idx = blockIdx.x * 256 + threadIdx.x;
    if (idx >= NB * Lc * 64) return;
    int c = idx & 63;
    int bt = idx >> 6;
    int t = bt % Lc;
    int b = bt / Lc;

    size_t vofs = ((size_t)b * NLEN + t) * 512 + c * 8;
    size_t uofs = ((size_t)b * NLEN + base_t + t) * 512 + c * 8;
    float ve[16];
#pragma unroll
    for (int k = 0; k < 8; k++) {
        ve[k] = vin[vofs + k] + Us[uofs + k];
        ve[8 + k] = Ud[uofs + k];
    }
    float xe[8] = {0}, xo[8] = {0};
#pragma unroll
    for (int kk = 0; kk < 16; kk++) {
        float xv = ve[kk];
#pragma unroll
        for (int k = 0; k < 8; k++) {
            xe[k] += xv * re[kk * 8 + k];
            xo[k] += xv * ro[kk * 8 + k];
        }
    }
    float* d0 = vout + ((size_t)b * NLEN + 2 * t) * 512 + c * 8;
    float* d1 = d0 + 512;
    ((float4*)d0)[0] = make_float4(xe[0], xe[1], xe[2], xe[3]);
    ((float4*)d0)[1] = make_float4(xe[4], xe[5], xe[6], xe[7]);
    ((float4*)d1)[0] = make_float4(xo[0], xo[1], xo[2], xo[3]);
    ((float4*)d1)[1] = make_float4(xo[4], xo[5], xo[6], xo[7]);
}

// ---------------- host orchestration ----------------
extern "C" void kernel_launch(void* const* d_in, const int* in_sizes, int n_in,
                              void* d_out, int out_size)
{
    const float* x     = (const float*)d_in[0];
    const float* Lk0_w = (const float*)d_in[1];
    const float* Lk0_b = (const float*)d_in[2];
    const float* Lk1_w = (const float*)d_in[3];
    const float* Lk1_b = (const float*)d_in[4];
    const float* T0_w  = (const float*)d_in[5];
    const float* T0_b  = (const float*)d_in[6];
    const float* Ar    = (const float*)d_in[7];
    const float* Ai    = (const float*)d_in[8];
    const float* Br    = (const float*)d_in[9];
    const float* Bi    = (const float*)d_in[10];
    const float* Cr    = (const float*)d_in[11];
    const float* Ci    = (const float*)d_in[12];
    const float* ec_s  = (const float*)d_in[13];
    const float* ec_d  = (const float*)d_in[14];
    const float* rc_e  = (const float*)d_in[15];
    const float* rc_o  = (const float*)d_in[16];

    float *vA, *vB, *dbuf, *DfR, *DfI, *SfR, *SfI, *UdFR, *UdFI, *UsFR, *UsFI, *Ud, *Us, *Wt;
    float2* tw; u64* part;
    cudaGetSymbolAddress((void**)&vA, g_vA);
    cudaGetSymbolAddress((void**)&vB, g_vB);
    cudaGetSymbolAddress((void**)&dbuf, g_dbuf);
    cudaGetSymbolAddress((void**)&DfR, g_DfR);
    cudaGetSymbolAddress((void**)&DfI, g_DfI);
    cudaGetSymbolAddress((void**)&SfR, g_SfR);
    cudaGetSymbolAddress((void**)&SfI, g_SfI);
    cudaGetSymbolAddress((void**)&UdFR, g_UdFR);
    cudaGetSymbolAddress((void**)&UdFI, g_UdFI);
    cudaGetSymbolAddress((void**)&UsFR, g_UsFR);
    cudaGetSymbolAddress((void**)&UsFI, g_UsFI);
    cudaGetSymbolAddress((void**)&Ud, g_Ud);
    cudaGetSymbolAddress((void**)&Us, g_Us);
    cudaGetSymbolAddress((void**)&Wt, g_Wt);
    cudaGetSymbolAddress((void**)&tw, g_tw);
    cudaGetSymbolAddress((void**)&part, g_part);

    // twiddle tables + weight transpose (independent)
    twiddle_kernel<<<dim3(128, NLVL), 256>>>(tw);
    transpose_w<<<dim3(4096, 6), 256>>>(Ar, Ai, Br, Bi, Cr, Ci, Wt);

    // Lk0 GEMM with wrap padding -> vA
    gemm_kernel<<<dim3(4, 128), 256>>>(x, Lk0_w, Lk0_b, vA, NB * NLEN, 0);

    // decomposition: filter -> fwd DFT partials -> reduce
    float* cur = vA;
    float* oth = vB;
    for (int j = 0; j < NLVL; j++) {
        int Lc = NLEN >> (j + 1);
        int toff = 16 * (4096 - (4096 >> j));
        int nblk = (NB * Lc * 64 + 255) / 256;
        filter_kernel<<<nblk, 256>>>(cur, oth, dbuf, Lc, ec_s, ec_d);
        int gz = Lc / 64; if (gz < 1) gz = 1; if (gz > 8) gz = 8;
        int CH = Lc / gz;
        fwd_dft2<<<dim3(32, 2, gz), 256>>>(Lc, CH, toff, dbuf, oth, tw, part);
        reduce_fwd<<<256, 256>>>(part, gz, j, DfR, DfI, SfR, SfI);
        float* tmp = cur; cur = oth; oth = tmp;
    }

    // batched spectral mixing
    mix_kernel<<<dim3(16, 8), 256>>>(Wt, DfR, DfI, SfR, SfI, UdFR, UdFI, UsFR, UsFI);

    // inverse partial DFTs
    for (int j = 0; j < NLVL; j++) {
        int Lc = NLEN >> (j + 1);
        int toff = 16 * (4096 - (4096 >> j));
        int nf = (Lc >> 1) + 1;
        int l = nf < 16 ? nf : 16;
        int nyq = (l == nf) ? 1 : 0;
        int base = NLEN - (NLEN >> j);
        int gz = Lc / 32; if (gz < 1) gz = 1; if (gz > 16) gz = 16;
        int CH = Lc / gz;
        inv_dft2<<<dim3(8, 4, gz), 256>>>(j, Lc, l, nyq, base, CH, toff,
                                          UdFR, UdFI, UsFR, UsFI, tw, Ud, Us);
    }

    // T0 on coarsest scale
    t0_kernel<<<1, 512>>>(cur, T0_w, T0_b);

    // reconstruction coarse -> fine
    for (int i = NLVL - 1; i >= 0; i--) {
        int Lc = NLEN >> (i + 1);
        int base = NLEN - (NLEN >> i);
        int nblk = (NB * Lc * 64 + 255) / 256;
        recon_kernel<<<nblk, 256>>>(cur, oth, Ud, Us, Lc, base, rc_e, rc_o);
        float* tmp = cur; cur = oth; oth = tmp;
    }

    // Lk1 GEMM (slice fused) -> d_out
    gemm_kernel<<<dim3(4, 96), 256>>>(cur, Lk1_w, Lk1_b, (float*)d_out, NB * LSEQ, 1);
}